// round 17
// baseline (speedup 1.0000x reference)
#include <cuda_runtime.h>
#include <cuda_fp16.h>
#include <cstdint>

#define NN   50000
#define EE   1600000
#define BB   64
#define DD   128
#define LL   3
#define OUTD 64

#define SCAN_B 196          // ceil(50000/256)
#define NT     391          // ceil(50000/128) MLP tiles

// ---------------- scratch (static device allocations; zero-init at load) ----------------
// INVARIANT: every kernel_launch execution leaves g_deg, g_counts, g_G zeroed
// (scan23 re-zeroes g_deg; final_kernel re-zeroes g_counts and g_G).
__device__ int            g_deg[NN];
__device__ int            g_offs[NN + 1];
__device__ int            g_rank[EE];     // per-edge rank within its dst segment
__device__ unsigned short g_csr[EE];     // node ids < 65536
__device__ int            g_counts[BB];
__device__ int            g_bsum[SCAN_B];
__device__ float          g_G[LL * DD];
__device__ __half         g_z16[NN * DD];
__device__ __half         g_x16[NN * DD];
__device__ __half         g_h16[LL][NN * DD];
__device__ __half         g_w1t[LL * DD * DD];   // transposed [n][k] fp16
__device__ __half         g_w2t[LL * DD * DD];   // transposed [n][k] fp16

// ---------------- prep: x->fp16 + weight transpose + degree hist (rank-recording) + batch hist ----
__global__ void prep_kernel(const float* __restrict__ x,
                            const float* __restrict__ W1g, const float* __restrict__ W2g,
                            const int* __restrict__ dst, const int* __restrict__ batch) {
    int i = blockIdx.x * blockDim.x + threadIdx.x;   // grid covers EE == NN*DD/4
    if (i < NN * DD / 4) {
        float4 v = ((const float4*)x)[i];
        __half2* o = (__half2*)(g_x16 + (size_t)i * 4);
        o[0] = __floats2half2_rn(v.x, v.y);
        o[1] = __floats2half2_rn(v.z, v.w);
    }
    if (i < LL * DD * DD / 2) {
        int l  = i / (DD * DD / 2);
        int r  = i % (DD * DD / 2);
        int n  = r / (DD / 2);
        int k  = (r % (DD / 2)) * 2;
        size_t gb = (size_t)l * DD * DD;
        float a0 = W1g[gb + (size_t)k * DD + n];
        float a1 = W1g[gb + (size_t)(k + 1) * DD + n];
        *(__half2*)(g_w1t + gb + (size_t)n * DD + k) = __floats2half2_rn(a0, a1);
        float b0v = W2g[gb + (size_t)k * DD + n];
        float b1v = W2g[gb + (size_t)(k + 1) * DD + n];
        *(__half2*)(g_w2t + gb + (size_t)n * DD + k) = __floats2half2_rn(b0v, b1v);
    }
    if (i < EE) {
        int p = atomicAdd(&g_deg[dst[i]], 1);   // rank = old count
        g_rank[i] = p;
    }
    unsigned act = __ballot_sync(0xffffffffu, i < NN);
    if (i < NN) {
        int b = batch[i];                      // sorted -> warps mostly uniform
        unsigned m = __match_any_sync(act, b);
        int leader = __ffs(m) - 1;
        if ((threadIdx.x & 31) == leader) atomicAdd(&g_counts[b], __popc(m));
    }
}

// ---- scan stage 1: per-block sums ----
__global__ void scan1_kernel() {
    int i = blockIdx.x * 256 + threadIdx.x;
    int v = (i < NN) ? g_deg[i] : 0;
#pragma unroll
    for (int d = 16; d > 0; d >>= 1) v += __shfl_down_sync(0xffffffffu, v, d);
    __shared__ int ws[8];
    if ((threadIdx.x & 31) == 0) ws[threadIdx.x >> 5] = v;
    __syncthreads();
    if (threadIdx.x < 8) {
        int t = ws[threadIdx.x];
#pragma unroll
        for (int d = 4; d > 0; d >>= 1) t += __shfl_down_sync(0xffu, t, d);
        if (threadIdx.x == 0) g_bsum[blockIdx.x] = t;
    }
}

// ---- scan stage 2+3 merged; re-zeroes g_deg after consuming it ----
__global__ void scan23_kernel() {
    __shared__ int bs[256];
    __shared__ int sh[256];
    int tid = threadIdx.x;
    bs[tid] = (tid < SCAN_B) ? g_bsum[tid] : 0;
    __syncthreads();
    for (int d = 1; d < 256; d <<= 1) {
        int t = (tid >= d) ? bs[tid - d] : 0;
        __syncthreads();
        bs[tid] += t;
        __syncthreads();
    }
    int base = (blockIdx.x == 0) ? 0 : bs[blockIdx.x - 1];

    int i = blockIdx.x * 256 + tid;
    int v = (i < NN) ? g_deg[i] : 0;
    if (i < NN) g_deg[i] = 0;               // restore invariant for next launch
    sh[tid] = v;
    __syncthreads();
    for (int d = 1; d < 256; d <<= 1) {
        int t = (tid >= d) ? sh[tid - d] : 0;
        __syncthreads();
        sh[tid] += t;
        __syncthreads();
    }
    if (i < NN) g_offs[i] = base + sh[tid] - v;
    if (blockIdx.x == 0 && tid == 0) g_offs[NN] = EE;
}

// ---------------- scatter: atomic-free (offs[dst] + rank) ----------------
__global__ void scatter_kernel(const int* __restrict__ src, const int* __restrict__ dst) {
    int i = blockIdx.x * blockDim.x + threadIdx.x;
    if (i < EE) {
        int d = dst[i];
        int pos = g_offs[d] + g_rank[i];
        g_csr[pos] = (unsigned short)src[i];
    }
}

// ---------------- aggregation: half-warp per node, fp16 gather, HADD2 pairs ----
__device__ __forceinline__ uint32_t hadd2u(uint32_t a, uint32_t b) {
    uint32_t r;
    asm("add.f16x2 %0, %1, %2;" : "=r"(r) : "r"(a), "r"(b));
    return r;
}

__global__ void agg_kernel(const float* __restrict__ eps, int l) {
    int node = (blockIdx.x * blockDim.x + threadIdx.x) >> 4;
    if (node >= NN) return;
    int lane = threadIdx.x & 15;

    const __half* hin16 = (l == 0) ? g_x16 : g_h16[l - 1];
    const uint4* hp = (const uint4*)hin16;   // 8 halves per uint4, row = 16 uint4

    float ep1 = 1.0f + eps[l];
    float acc[8];
    {
        uint4 sv = hp[(size_t)node * 16 + lane];
        const __half2* s = (const __half2*)&sv;
#pragma unroll
        for (int q = 0; q < 4; q++) {
            float2 f = __half22float2(s[q]);
            acc[2 * q]     = f.x * ep1;
            acc[2 * q + 1] = f.y * ep1;
        }
    }

    int s = g_offs[node], e = g_offs[node + 1];
    int j = s;
    for (; j + 8 <= e; j += 8) {
        uint4 v[8];
#pragma unroll
        for (int q = 0; q < 8; q++) v[q] = hp[(size_t)g_csr[j + q] * 16 + lane];
#pragma unroll
        for (int pr = 0; pr < 4; pr++) {
#pragma unroll
            for (int p = 0; p < 4; p++) {
                uint32_t ps = hadd2u((&v[2 * pr].x)[p], (&v[2 * pr + 1].x)[p]);
                float2 f = __half22float2(*reinterpret_cast<__half2*>(&ps));
                acc[2 * p]     += f.x;
                acc[2 * p + 1] += f.y;
            }
        }
    }
    for (; j < e; j++) {
        uint4 v = hp[(size_t)g_csr[j] * 16 + lane];
#pragma unroll
        for (int p = 0; p < 4; p++) {
            uint32_t u = (&v.x)[p];
            float2 f = __half22float2(*reinterpret_cast<__half2*>(&u));
            acc[2 * p]     += f.x;
            acc[2 * p + 1] += f.y;
        }
    }

    uint4 ov;
    __half2* oh = (__half2*)&ov;
    oh[0] = __floats2half2_rn(acc[0], acc[1]);
    oh[1] = __floats2half2_rn(acc[2], acc[3]);
    oh[2] = __floats2half2_rn(acc[4], acc[5]);
    oh[3] = __floats2half2_rn(acc[6], acc[7]);
    ((uint4*)g_z16)[(size_t)node * 16 + lane] = ov;
}

// ---------------- fp16 tensor-core persistent MLP + fused pooling ----------------
#define ZP 136                 // halves per smem row (stride 272B)
#define MLP_SMEM (3 * 128 * ZP * 2)

__device__ __forceinline__ void mma_f16(float c[4], const uint32_t a[4], const uint32_t b0, const uint32_t b1) {
    asm volatile(
        "mma.sync.aligned.m16n8k16.row.col.f32.f16.f16.f32 "
        "{%0,%1,%2,%3}, {%4,%5,%6,%7}, {%8,%9}, {%0,%1,%2,%3};\n"
        : "+f"(c[0]), "+f"(c[1]), "+f"(c[2]), "+f"(c[3])
        : "r"(a[0]), "r"(a[1]), "r"(a[2]), "r"(a[3]), "r"(b0), "r"(b1));
}

__device__ __forceinline__ void ldm_x4(uint32_t& r0, uint32_t& r1, uint32_t& r2, uint32_t& r3, uint32_t a) {
    asm volatile("ldmatrix.sync.aligned.m8n8.x4.shared.b16 {%0,%1,%2,%3}, [%4];"
                 : "=r"(r0), "=r"(r1), "=r"(r2), "=r"(r3) : "r"(a));
}

__device__ __forceinline__ void gemm_tile16(const __half* __restrict__ Zs, const __half* __restrict__ Ws,
                                            float acc[2][8][4], int wm, int wn, int lane) {
    uint32_t za = (uint32_t)__cvta_generic_to_shared(Zs);
    uint32_t wa = (uint32_t)__cvta_generic_to_shared(Ws);
    int l8    = lane & 7;
    int half8 = (lane >> 3) & 1;
    int hi16  = lane >> 4;

    uint32_t a_off[2];
#pragma unroll
    for (int mt = 0; mt < 2; mt++)
        a_off[mt] = za + (uint32_t)(((wm + mt * 16 + half8 * 8 + l8) * ZP + hi16 * 8) * 2);
    uint32_t b_off[4];
#pragma unroll
    for (int i = 0; i < 4; i++)
        b_off[i] = wa + (uint32_t)(((wn + i * 16 + hi16 * 8 + l8) * ZP + half8 * 8) * 2);

#pragma unroll
    for (int k0 = 0; k0 < 128; k0 += 16) {
        uint32_t a[2][4], b[4][4];
        ldm_x4(a[0][0], a[0][1], a[0][2], a[0][3], a_off[0] + k0 * 2);
        ldm_x4(a[1][0], a[1][1], a[1][2], a[1][3], a_off[1] + k0 * 2);
#pragma unroll
        for (int i = 0; i < 4; i++)
            ldm_x4(b[i][0], b[i][1], b[i][2], b[i][3], b_off[i] + k0 * 2);
#pragma unroll
        for (int mt = 0; mt < 2; mt++)
#pragma unroll
            for (int nt = 0; nt < 8; nt++)
                mma_f16(acc[mt][nt], a[mt], b[nt >> 1][(nt & 1) * 2], b[nt >> 1][(nt & 1) * 2 + 1]);
    }
}

__global__ __launch_bounds__(256, 2) void mlp_kernel(
    int l, const int* __restrict__ batch,
    const float* __restrict__ b1g, const float* __restrict__ b2g) {
    extern __shared__ __half hsm[];
    __half* Zs  = hsm;               // [128][ZP]
    __half* W1s = hsm + 128 * ZP;    // [128][ZP]
    __half* W2s = hsm + 2 * 128 * ZP;
    __shared__ float inv_s[128];
    __shared__ float pool2[128];     // second-half pool partials
    const __half* W1t = g_w1t + (size_t)l * DD * DD;
    const __half* W2t = g_w2t + (size_t)l * DD * DD;
    const float* b1 = b1g + l * DD;
    const float* b2 = b2g + l * DD;
    __half* hout16 = g_h16[l];

    int tid  = threadIdx.x;
    int lane = tid & 31;
    int w    = tid >> 5;
    int wm   = (w & 3) * 32;
    int wn   = (w >> 2) * 64;

    // load both weight tiles once per block
#pragma unroll
    for (int i = 0; i < 8; i++) {
        int idx = i * 256 + tid;
        int row = idx >> 4;
        int c8  = (idx & 15) * 8;
        *(uint4*)(W1s + row * ZP + c8) = *(const uint4*)(W1t + (size_t)row * DD + c8);
        *(uint4*)(W2s + row * ZP + c8) = *(const uint4*)(W2t + (size_t)row * DD + c8);
    }

    for (int t = blockIdx.x; t < NT; t += gridDim.x) {
        int m0 = t * 128;
        __syncthreads();   // weights ready (iter0) / prev-tile smem reads done

        // load Z tile + per-row pool weights
#pragma unroll
        for (int i = 0; i < 8; i++) {
            int idx = i * 256 + tid;
            int row = idx >> 4;
            int c8  = (idx & 15) * 8;
            uint4 v = make_uint4(0u, 0u, 0u, 0u);
            if (m0 + row < NN) v = *(const uint4*)(g_z16 + (size_t)(m0 + row) * DD + c8);
            *(uint4*)(Zs + row * ZP + c8) = v;
        }
        if (tid < 128) {
            int row = m0 + tid;
            float iv = 0.f;
            if (row < NN) iv = 1.f / (float)max(g_counts[batch[row]], 1);
            inv_s[tid] = iv;
        }
        __syncthreads();

        float acc[2][8][4];
#pragma unroll
        for (int mt = 0; mt < 2; mt++)
#pragma unroll
            for (int nt = 0; nt < 8; nt++)
#pragma unroll
                for (int i = 0; i < 4; i++) acc[mt][nt][i] = 0.f;

        gemm_tile16(Zs, W1s, acc, wm, wn, lane);
        __syncthreads();

        // epilogue1: relu(acc + b1) -> Zs
        {
            int g = lane >> 2, tt = lane & 3;
#pragma unroll
            for (int nt = 0; nt < 8; nt++) {
                int col = wn + nt * 8 + 2 * tt;
                float bx = __ldg(b1 + col), by = __ldg(b1 + col + 1);
#pragma unroll
                for (int mt = 0; mt < 2; mt++) {
                    int r0 = wm + mt * 16 + g;
                    *(__half2*)(Zs + r0 * ZP + col) =
                        __floats2half2_rn(fmaxf(acc[mt][nt][0] + bx, 0.f), fmaxf(acc[mt][nt][1] + by, 0.f));
                    *(__half2*)(Zs + (r0 + 8) * ZP + col) =
                        __floats2half2_rn(fmaxf(acc[mt][nt][2] + bx, 0.f), fmaxf(acc[mt][nt][3] + by, 0.f));
                }
            }
        }
        __syncthreads();

#pragma unroll
        for (int mt = 0; mt < 2; mt++)
#pragma unroll
            for (int nt = 0; nt < 8; nt++)
#pragma unroll
                for (int i = 0; i < 4; i++) acc[mt][nt][i] = 0.f;

        gemm_tile16(Zs, W2s, acc, wm, wn, lane);
        __syncthreads();

        // epilogue2: acc + b2 -> Zs staging
        {
            int g = lane >> 2, tt = lane & 3;
#pragma unroll
            for (int nt = 0; nt < 8; nt++) {
                int col = wn + nt * 8 + 2 * tt;
                float bx = __ldg(b2 + col), by = __ldg(b2 + col + 1);
#pragma unroll
                for (int mt = 0; mt < 2; mt++) {
                    int r0 = wm + mt * 16 + g;
                    *(__half2*)(Zs + r0 * ZP + col) =
                        __floats2half2_rn(acc[mt][nt][0] + bx, acc[mt][nt][1] + by);
                    *(__half2*)(Zs + (r0 + 8) * ZP + col) =
                        __floats2half2_rn(acc[mt][nt][2] + bx, acc[mt][nt][3] + by);
                }
            }
        }
        __syncthreads();
        // coalesced store of h + fused mean-pool partial (split across both half-blocks)
#pragma unroll
        for (int i = 0; i < 8; i++) {
            int idx = i * 256 + tid;
            int row = idx >> 4;
            int c8  = (idx & 15) * 8;
            if (m0 + row < NN)
                *(uint4*)(hout16 + (size_t)(m0 + row) * DD + c8) = *(const uint4*)(Zs + row * ZP + c8);
        }
        {
            int col  = tid & 127;
            int half = tid >> 7;          // 0: rows 0-63, 1: rows 64-127
            int rmax = NN - m0;
            float a = 0.f;
            int rlo = half * 64;
            int rhi = min(rlo + 64, rmax);
            for (int r = rlo; r < rhi; r++)
                a += __half2float(Zs[r * ZP + col]) * inv_s[r];
            if (half == 1) pool2[col] = a;
            __syncthreads();
            if (half == 0) atomicAdd(&g_G[l * DD + col], a + pool2[col]);
        }
    }
}

// ---------------- final tiny MLP (restores g_G/g_counts invariant) ----------------
__global__ void final_kernel(const float* __restrict__ l1w, const float* __restrict__ l1b,
                             const float* __restrict__ l2w, const float* __restrict__ l2b,
                             float* __restrict__ out) {
    __shared__ float Gs[LL * DD];
    __shared__ float part[8][DD];
    __shared__ float g1[DD];
    int tid = threadIdx.x;  // 1024
    if (tid < LL * DD) Gs[tid] = g_G[tid];
    __syncthreads();
    if (tid < LL * DD) g_G[tid] = 0.f;      // restore invariant
    if (tid < BB) g_counts[tid] = 0;        // restore invariant
    {
        int o  = tid & 127;
        int sl = tid >> 7;       // 0..7, 48 k-values each
        float a = 0.f;
        int k0 = sl * 48;
#pragma unroll 4
        for (int k = k0; k < k0 + 48; k++) a += Gs[k] * l1w[(size_t)k * DD + o];
        part[sl][o] = a;
    }
    __syncthreads();
    if (tid < DD) {
        float s = l1b[tid];
#pragma unroll
        for (int j = 0; j < 8; j++) s += part[j][tid];
        g1[tid] = fmaxf(s, 0.f);
    }
    __syncthreads();
    if (tid < OUTD) {
        float a2 = l2b[tid];
#pragma unroll 4
        for (int k = 0; k < DD; k++) a2 += g1[k] * l2w[k * OUTD + tid];
        out[tid] = fmaxf(a2, 0.f);
    }
}

// ---------------- launch (single stream) ----------------
extern "C" void kernel_launch(void* const* d_in, const int* in_sizes, int n_in,
                              void* d_out, int out_size) {
    const float* x    = (const float*)d_in[0];
    const int*   ei   = (const int*)d_in[1];
    const int*   batch= (const int*)d_in[2];
    const float* eps  = (const float*)d_in[3];
    const float* W1   = (const float*)d_in[4];
    const float* b1   = (const float*)d_in[5];
    const float* W2   = (const float*)d_in[6];
    const float* b2   = (const float*)d_in[7];
    const float* l1w  = (const float*)d_in[8];
    const float* l1b  = (const float*)d_in[9];
    const float* l2w  = (const float*)d_in[10];
    const float* l2b  = (const float*)d_in[11];
    float* out = (float*)d_out;

    cudaFuncSetAttribute(mlp_kernel, cudaFuncAttributeMaxDynamicSharedMemorySize, MLP_SMEM);

    prep_kernel<<<(EE + 255) / 256, 256>>>(x, W1, W2, ei + EE, batch);
    scan1_kernel<<<SCAN_B, 256>>>();
    scan23_kernel<<<SCAN_B, 256>>>();
    scatter_kernel<<<(EE + 255) / 256, 256>>>(ei, ei + EE);   // <- ncu slot 4 (now atomic-free)

    for (int l = 0; l < LL; l++) {
        agg_kernel<<<(NN * 16 + 255) / 256, 256>>>(eps, l);
        mlp_kernel<<<296, 256, MLP_SMEM>>>(l, batch, b1, b2);
    }

    final_kernel<<<1, 1024>>>(l1w, l1b, l2w, l2b, out);
}